// round 14
// baseline (speedup 1.0000x reference)
#include <cuda_runtime.h>
#include <cuda_fp16.h>
#include <cstdint>

// ---------------------------------------------------------------------------
// LocalAttentionBlock on GB300 (sm_103 base PTX — no tcgen05):
//   GEMMs: plain fp16, 256x128 CTA tiles (16 warps), STG=4 single-barrier ring.
//   Attention: FA2 fp16, 128-query x 2-head CTAs, 3-stage ring.
// b=2, t=2048, WIDTH=1024, HEADS=16, HEAD_DIM=64, WINDOW=256
// ---------------------------------------------------------------------------

#define B_    2
#define T_    2048
#define M_    (B_ * T_)        // 4096 rows
#define WID_  1024
#define NH_   16
#define HD_   64
#define WIN_  256
#define KW_   1024
#define NQKV  1152             // 1024 Q + 64 K + 64 V output cols

// ----- scratch (device globals; no allocations allowed) -----
__device__ __half g_Xs   [(size_t)M_ * KW_];
__device__ __half g_As   [(size_t)M_ * KW_];
__device__ __half g_Wqkvs[(size_t)NQKV * KW_];
__device__ __half g_Wfs  [(size_t)WID_ * KW_];
__device__ __half g_Qh   [(size_t)M_ * WID_];         // [m][h*64+d], pre-scaled 1/8
__device__ __half g_Ks   [(size_t)M_ * HD_];          // [m][d]
__device__ __half g_Vt   [(size_t)B_ * HD_ * T_];     // [b][d][t]

// ---------------------------------------------------------------------------
__device__ __forceinline__ uint32_t smem_u32(const void* p) {
    uint32_t a;
    asm("{ .reg .u64 t; cvta.to.shared.u64 t, %1; cvt.u32.u64 %0, t; }"
        : "=r"(a) : "l"(p));
    return a;
}
#define CP_ASYNC16(dst, src) \
    asm volatile("cp.async.cg.shared.global [%0], [%1], 16;" \
        :: "r"(dst), "l"(src) : "memory")
#define CP_COMMIT() asm volatile("cp.async.commit_group;" ::: "memory")
#define CP_WAIT(n)  asm volatile("cp.async.wait_group %0;" :: "n"(n) : "memory")
#define LDSM_X4(r0, r1, r2, r3, addr) \
    asm volatile("ldmatrix.sync.aligned.m8n8.x4.shared.b16 {%0,%1,%2,%3}, [%4];" \
        : "=r"(r0), "=r"(r1), "=r"(r2), "=r"(r3) : "r"(addr))
#define MMA_FP16(d, a, b0, b1) \
    asm volatile("mma.sync.aligned.m16n8k16.row.col.f32.f16.f16.f32 " \
        "{%0,%1,%2,%3}, {%4,%5,%6,%7}, {%8,%9}, {%0,%1,%2,%3};" \
        : "+f"((d)[0]), "+f"((d)[1]), "+f"((d)[2]), "+f"((d)[3]) \
        : "r"((a)[0]), "r"((a)[1]), "r"((a)[2]), "r"((a)[3]), "r"(b0), "r"(b1))

__device__ __forceinline__ uint32_t packh2(float a, float b) {
    __half2 h = __floats2half2_rn(a, b);
    return *reinterpret_cast<uint32_t*>(&h);
}

// ---------------------------------------------------------------------------
// Fused conversion: x then [Wq|Wk|Wv|Wf], all hi-only fp16, float4-vectorized.
// ---------------------------------------------------------------------------
#define XV4 (M_ * WID_ / 4)
#define WV4 ((NQKV + WID_) * WID_ / 4)

__global__ __launch_bounds__(256)
void conv_all(const float4* __restrict__ x,
              const float4* __restrict__ Wq, const float4* __restrict__ Wk,
              const float4* __restrict__ Wv, const float4* __restrict__ Wf) {
    int idx = blockIdx.x * 256 + threadIdx.x;
    if (idx < XV4) {
        float4 v = x[idx];
        *(uint2*)&g_Xs[(size_t)idx * 4] =
            make_uint2(packh2(v.x, v.y), packh2(v.z, v.w));
        return;
    }
    int wi = idx - XV4;
    if (wi >= WV4) return;
    int r = wi >> 8, k4 = wi & 255;
    float4 v;
    __half* dst;
    if (r < 1024)      { v = Wq[wi];                       dst = g_Wqkvs; }
    else if (r < 1088) { v = Wk[(r - 1024) * 256 + k4];    dst = g_Wqkvs; }
    else if (r < NQKV) { v = Wv[(r - 1088) * 256 + k4];    dst = g_Wqkvs; }
    else               { v = Wf[(r - NQKV) * 256 + k4];    dst = g_Wfs; r -= NQKV; }
    *(uint2*)&dst[(size_t)r * KW_ + k4 * 4] =
        make_uint2(packh2(v.x, v.y), packh2(v.z, v.w));
}

// ---------------------------------------------------------------------------
// mma.sync fp16 GEMM: C[M,N] = A[M,1024] * B[N,1024]^T.
// CTA 256x128, 16 warps (8M x 2N), warp tile 32x64. KC=32, 4-stage ring,
// ONE barrier/chunk (prefetch distance 2 on ring 4: writer never aliases a
// buffer a warp lagging at chunk c-1 may read).
// MODE 0: fp32 out + bias.  MODE 1: fused QKV epilogue (Q pre-scaled 1/8).
// ---------------------------------------------------------------------------
#define KC 32
#define ROWT 80            // 32 halfs + 16B pad
#define STG 4
#define ABUF (256 * ROWT)  // 20480
#define BBUF (128 * ROWT)  // 10240
#define GSMEM (STG * (ABUF + BBUF))   // 122880

template <int MODE>
__global__ __launch_bounds__(512, 1)
void gemm_mma(const __half* __restrict__ A, const __half* __restrict__ B,
              float* __restrict__ C, const float* __restrict__ bias, int N) {
    extern __shared__ __align__(16) char sm[];
    const uint32_t sA = smem_u32(sm);
    const uint32_t sB = sA + STG * ABUF;

    const int tid  = threadIdx.x;
    const int wid  = tid >> 5;
    const int lane = tid & 31;
    const int wm = (wid & 7) * 32;       // 8 m-slots
    const int wn = (wid >> 3) * 64;      // 2 n-slots
    const int bm = blockIdx.y;
    const int bn = blockIdx.x;

    const char* Ab = (const char*)(A + (size_t)bm * 256 * KW_);
    const char* Bb = (const char*)(B + (size_t)bn * 128 * KW_);

    float acc[2][8][4];
    #pragma unroll
    for (int i = 0; i < 2; i++)
        #pragma unroll
        for (int j = 0; j < 8; j++)
            #pragma unroll
            for (int q = 0; q < 4; q++) acc[i][j][q] = 0.f;

    const int nc = KW_ / KC;    // 32 chunks

    auto prefetch = [&](int ck) {
        const int buf = ck & (STG - 1);
        uint32_t as = sA + buf * ABUF;
        uint32_t bs = sB + buf * BBUF;
        const char* ag = Ab + ck * (KC * 2);
        const char* bg = Bb + ck * (KC * 2);
        // A: 256 rows x 4 vec16 = 1024 vecs, 2 per thread
        #pragma unroll
        for (int t = 0; t < 2; t++) {
            int v = tid + t * 512;
            int row = v >> 2, c16 = (v & 3) * 16;
            CP_ASYNC16(as + row * ROWT + c16, ag + (size_t)row * 2048 + c16);
        }
        // B: 128 rows x 4 vec16 = 512 vecs, 1 per thread
        {
            int row = tid >> 2, c16 = (tid & 3) * 16;
            CP_ASYNC16(bs + row * ROWT + c16, bg + (size_t)row * 2048 + c16);
        }
    };

    prefetch(0); CP_COMMIT();
    prefetch(1); CP_COMMIT();

    const int a_r = lane & 15;
    const int a_c = (lane >> 4) * 16;
    const int b_r = (lane & 7) | ((lane >> 4) << 3);
    const int b_c = ((lane >> 3) & 1) * 16;

    for (int ck = 0; ck < nc; ck++) {
        if (ck + 2 < nc) { prefetch(ck + 2); CP_COMMIT(); CP_WAIT(2); }
        else if (ck + 1 < nc) CP_WAIT(1);
        else CP_WAIT(0);
        __syncthreads();

        const int buf = ck & (STG - 1);
        const uint32_t as = sA + buf * ABUF;
        const uint32_t bs = sB + buf * BBUF;

        #pragma unroll
        for (int ks = 0; ks < 2; ks++) {
            uint32_t af[2][4];
            #pragma unroll
            for (int mt = 0; mt < 2; mt++) {
                uint32_t base = as + (wm + mt * 16 + a_r) * ROWT + ks * 32 + a_c;
                LDSM_X4(af[mt][0], af[mt][1], af[mt][2], af[mt][3], base);
            }
            uint32_t bf2[4][4];
            #pragma unroll
            for (int nt = 0; nt < 4; nt++) {
                uint32_t addr = bs + (wn + nt * 16 + b_r) * ROWT + ks * 32 + b_c;
                LDSM_X4(bf2[nt][0], bf2[nt][1], bf2[nt][2], bf2[nt][3], addr);
            }
            #pragma unroll
            for (int mt = 0; mt < 2; mt++)
                #pragma unroll
                for (int n8 = 0; n8 < 8; n8++)
                    MMA_FP16(acc[mt][n8], af[mt],
                             bf2[n8 >> 1][(n8 & 1) * 2], bf2[n8 >> 1][(n8 & 1) * 2 + 1]);
        }
    }

    const int gid = lane >> 2;
    const int tig = lane & 3;
    #pragma unroll
    for (int mt = 0; mt < 2; mt++) {
        #pragma unroll
        for (int n8 = 0; n8 < 8; n8++) {
            int col  = bn * 128 + wn + n8 * 8 + tig * 2;
            int row0 = bm * 256 + wm + mt * 16 + gid;
            if (MODE == 0) {
                float bx = bias[col], by = bias[col + 1];
                float2 v0 = make_float2(acc[mt][n8][0] + bx, acc[mt][n8][1] + by);
                float2 v1 = make_float2(acc[mt][n8][2] + bx, acc[mt][n8][3] + by);
                *(float2*)&C[(size_t)row0 * N + col] = v0;
                *(float2*)&C[(size_t)(row0 + 8) * N + col] = v1;
            } else {
                #pragma unroll
                for (int rh = 0; rh < 2; rh++) {
                    int rr = row0 + rh * 8;
                    float va = acc[mt][n8][rh * 2], vb = acc[mt][n8][rh * 2 + 1];
                    if (col < 1024) {
                        *(uint32_t*)&g_Qh[(size_t)rr * WID_ + col] =
                            packh2(va * 0.125f, vb * 0.125f);
                    } else if (col < 1088) {
                        int d = col - 1024;
                        *(uint32_t*)&g_Ks[(size_t)rr * HD_ + d] = packh2(va, vb);
                    } else {
                        int d = col - 1088;
                        int bb = rr >> 11, t = rr & 2047;
                        g_Vt[((size_t)bb * 64 + d)     * 2048 + t] = __float2half_rn(va);
                        g_Vt[((size_t)bb * 64 + d + 1) * 2048 + t] = __float2half_rn(vb);
                    }
                }
            }
        }
    }
}

// ---------------------------------------------------------------------------
// FA2-style sliding-window attention, pure fp16 mma, 3-stage smem ring.
// CTA = 128 queries x 2 heads (16 warps).
// ---------------------------------------------------------------------------
#define KROW 144
#define VROW 144
#define KBUF (64 * KROW)
#define VBUF (64 * VROW)
#define CHBUF (KBUF + VBUF)
#define ASTG 3
#define NCH  6

__global__ __launch_bounds__(512)
void attn_mma(void) {
    extern __shared__ __align__(16) char sm[];
    const uint32_t sb = smem_u32(sm);

    const int tid  = threadIdx.x;
    const int wid  = tid >> 5;
    const int lane = tid & 31;
    const int gid  = lane >> 2;
    const int tig  = lane & 3;
    const int b    = blockIdx.z;
    const int q0   = blockIdx.x * 128;
    const int h    = blockIdx.y * 2 + (wid >> 3);
    const int qrow = q0 + (wid & 7) * 16;
    const int m0   = b * T_ + qrow;

    uint32_t qh[4][4];
    {
        const size_t r0 = (size_t)(m0 + gid) * WID_ + h * 64;
        const size_t r1 = (size_t)(m0 + gid + 8) * WID_ + h * 64;
        #pragma unroll
        for (int kt = 0; kt < 4; kt++) {
            int c = kt * 16 + tig * 2;
            qh[kt][0] = *(const uint32_t*)&g_Qh[r0 + c];
            qh[kt][1] = *(const uint32_t*)&g_Qh[r1 + c];
            qh[kt][2] = *(const uint32_t*)&g_Qh[r0 + c + 8];
            qh[kt][3] = *(const uint32_t*)&g_Qh[r1 + c + 8];
        }
    }

    float D[8][4];
    #pragma unroll
    for (int i = 0; i < 8; i++)
        #pragma unroll
        for (int j = 0; j < 4; j++) D[i][j] = 0.f;
    float l0 = 0.f, l1 = 0.f;

    const int c_start = (q0 >= WIN_) ? 0 : (WIN_ - q0) / 64;

    auto load_chunk = [&](int c) {
        const int kc = q0 - WIN_ + c * 64;
        const uint32_t kb = sb + (c % ASTG) * CHBUF;
        const uint32_t vb = kb + KBUF;
        {
            int row = tid >> 3, c16 = (tid & 7) * 16;
            CP_ASYNC16(kb + row * KROW + c16,
                       (const char*)g_Ks + ((size_t)(b * T_ + kc + row) * HD_) * 2 + c16);
        }
        {
            int d = tid >> 3, c16 = (tid & 7) * 16;
            CP_ASYNC16(vb + d * VROW + c16,
                       (const char*)g_Vt + ((size_t)(b * 64 + d) * 2048 + kc) * 2 + c16);
        }
    };

    load_chunk(c_start);
    CP_COMMIT();

    const int b_r = (lane & 7) | ((lane >> 4) << 3);
    const int b_c = ((lane >> 3) & 1) * 16;
    const int qp0 = qrow + gid;
    const int qp1 = qrow + gid + 8;

    for (int c = c_start; c < NCH; c++) {
        if (c < NCH - 1) { load_chunk(c + 1); CP_COMMIT(); CP_WAIT(1); }
        else             { CP_WAIT(0); }
        __syncthreads();

        const int kc = q0 - WIN_ + c * 64;
        const uint32_t kb = sb + (c % ASTG) * CHBUF;
        const uint32_t vb = kb + KBUF;

        float S[8][4];
        #pragma unroll
        for (int i = 0; i < 8; i++)
            #pragma unroll
            for (int j = 0; j < 4; j++) S[i][j] = 0.f;

        #pragma unroll
        for (int kt = 0; kt < 4; kt++) {
            uint32_t bh[4][4];
            #pragma unroll
            for (int nt = 0; nt < 4; nt++)
                LDSM_X4(bh[nt][0], bh[nt][1], bh[nt][2], bh[nt][3],
                        kb + (nt * 16 + b_r) * KROW + kt * 32 + b_c);
            #pragma unroll
            for (int n8 = 0; n8 < 8; n8++)
                MMA_FP16(S[n8], qh[kt], bh[n8 >> 1][(n8 & 1) * 2], bh[n8 >> 1][(n8 & 1) * 2 + 1]);
        }

        #pragma unroll
        for (int s = 0; s < 4; s++) {
            uint32_t pa[4];
            #pragma unroll
            for (int half = 0; half < 2; half++) {
                int tile = 2 * s + half;
                float pe[4];
                #pragma unroll
                for (int e = 0; e < 4; e++) {
                    int ka  = kc + 8 * tile + 2 * tig + (e & 1);
                    int row = (e < 2) ? qp0 : qp1;
                    bool valid = (ka <= row) && (ka + WIN_ >= row);
                    pe[e] = valid ? __expf(S[tile][e]) : 0.f;
                }
                l0 += pe[0] + pe[1];
                l1 += pe[2] + pe[3];
                pa[half * 2 + 0] = packh2(pe[0], pe[1]);
                pa[half * 2 + 1] = packh2(pe[2], pe[3]);
            }

            uint32_t bv[4][4];
            #pragma unroll
            for (int nt = 0; nt < 4; nt++)
                LDSM_X4(bv[nt][0], bv[nt][1], bv[nt][2], bv[nt][3],
                        vb + (nt * 16 + b_r) * VROW + s * 32 + b_c);
            #pragma unroll
            for (int dt = 0; dt < 8; dt++)
                MMA_FP16(D[dt], pa, bv[dt >> 1][(dt & 1) * 2], bv[dt >> 1][(dt & 1) * 2 + 1]);
        }
    }

    l0 += __shfl_xor_sync(0xFFFFFFFFu, l0, 1);
    l0 += __shfl_xor_sync(0xFFFFFFFFu, l0, 2);
    l1 += __shfl_xor_sync(0xFFFFFFFFu, l1, 1);
    l1 += __shfl_xor_sync(0xFFFFFFFFu, l1, 2);
    const float inv0 = 1.f / l0;
    const float inv1 = 1.f / l1;

    const size_t r0m = (size_t)(m0 + gid) * KW_;
    const size_t r1m = (size_t)(m0 + gid + 8) * KW_;
    #pragma unroll
    for (int dt = 0; dt < 8; dt++) {
        int col = h * 64 + dt * 8 + tig * 2;
        *(uint32_t*)&g_As[r0m + col] = packh2(D[dt][0] * inv0, D[dt][1] * inv0);
        *(uint32_t*)&g_As[r1m + col] = packh2(D[dt][2] * inv1, D[dt][3] * inv1);
    }
}

// ---------------------------------------------------------------------------
extern "C" void kernel_launch(void* const* d_in, const int* in_sizes, int n_in,
                              void* d_out, int out_size) {
    const float* x  = (const float*)d_in[0];
    const float* Wq = (const float*)d_in[2];
    const float* Wk = (const float*)d_in[3];
    const float* Wv = (const float*)d_in[4];
    const float* Wf = (const float*)d_in[5];
    const float* bf = (const float*)d_in[6];
    float* out = (float*)d_out;

    __half *Xs, *As, *Wqkvs, *Wfs;
    cudaGetSymbolAddress((void**)&Xs,    g_Xs);
    cudaGetSymbolAddress((void**)&As,    g_As);
    cudaGetSymbolAddress((void**)&Wqkvs, g_Wqkvs);
    cudaGetSymbolAddress((void**)&Wfs,   g_Wfs);

    static int init = 0;
    if (!init) {
        cudaFuncSetAttribute(attn_mma, cudaFuncAttributeMaxDynamicSharedMemorySize,
                             ASTG * CHBUF);
        cudaFuncSetAttribute((const void*)gemm_mma<1>,
                             cudaFuncAttributeMaxDynamicSharedMemorySize, GSMEM);
        cudaFuncSetAttribute((const void*)gemm_mma<0>,
                             cudaFuncAttributeMaxDynamicSharedMemorySize, GSMEM);
        init = 1;
    }

    // fused conversions (hi-only fp16)
    conv_all<<<(XV4 + WV4 + 255) / 256, 256>>>(
        (const float4*)x, (const float4*)Wq, (const float4*)Wk,
        (const float4*)Wv, (const float4*)Wf);

    // fused QKV projection (256x128 tiles: 9x16 = 144 CTAs, 1 clean wave)
    gemm_mma<1><<<dim3(NQKV / 128, M_ / 256), 512, GSMEM>>>(Xs, Wqkvs, nullptr, nullptr, NQKV);

    // attention (fp16 tensor cores, 128-query tiles)
    attn_mma<<<dim3(T_ / 128, NH_ / 2, B_), 512, ASTG * CHBUF>>>();

    // output projection (+bias; 8x16 = 128 CTAs)
    gemm_mma<0><<<dim3(WID_ / 128, M_ / 256), 512, GSMEM>>>(As, Wfs, out, bf, WID_);
}

// round 15
// speedup vs baseline: 1.0550x; 1.0550x over previous
#include <cuda_runtime.h>
#include <cuda_fp16.h>
#include <cstdint>

// ---------------------------------------------------------------------------
// LocalAttentionBlock on GB300 (sm_103 base PTX — no tcgen05):
//   GEMMs: plain fp16, 128x128 tiles, 2 CTA/SM, STG=4 single-barrier ring.
//   Attention: FA2 fp16, 128-query x 2-head CTAs, exp2 + 1-compare masks.
// b=2, t=2048, WIDTH=1024, HEADS=16, HEAD_DIM=64, WINDOW=256
// ---------------------------------------------------------------------------

#define B_    2
#define T_    2048
#define M_    (B_ * T_)        // 4096 rows
#define WID_  1024
#define NH_   16
#define HD_   64
#define WIN_  256
#define KW_   1024
#define NQKV  1152             // 1024 Q + 64 K + 64 V output cols

// Q prescale: (1/sqrt(64)) * log2(e), folded so softmax uses exp2 directly.
#define QSCALE 0.1803368801111191f

// ----- scratch (device globals; no allocations allowed) -----
__device__ __half g_Xs   [(size_t)M_ * KW_];
__device__ __half g_As   [(size_t)M_ * KW_];
__device__ __half g_Wqkvs[(size_t)NQKV * KW_];
__device__ __half g_Wfs  [(size_t)WID_ * KW_];
__device__ __half g_Qh   [(size_t)M_ * WID_];         // [m][h*64+d], pre-scaled
__device__ __half g_Ks   [(size_t)M_ * HD_];          // [m][d]
__device__ __half g_Vt   [(size_t)B_ * HD_ * T_];     // [b][d][t]

// ---------------------------------------------------------------------------
__device__ __forceinline__ uint32_t smem_u32(const void* p) {
    uint32_t a;
    asm("{ .reg .u64 t; cvta.to.shared.u64 t, %1; cvt.u32.u64 %0, t; }"
        : "=r"(a) : "l"(p));
    return a;
}
#define CP_ASYNC16(dst, src) \
    asm volatile("cp.async.cg.shared.global [%0], [%1], 16;" \
        :: "r"(dst), "l"(src) : "memory")
#define CP_COMMIT() asm volatile("cp.async.commit_group;" ::: "memory")
#define CP_WAIT(n)  asm volatile("cp.async.wait_group %0;" :: "n"(n) : "memory")
#define LDSM_X4(r0, r1, r2, r3, addr) \
    asm volatile("ldmatrix.sync.aligned.m8n8.x4.shared.b16 {%0,%1,%2,%3}, [%4];" \
        : "=r"(r0), "=r"(r1), "=r"(r2), "=r"(r3) : "r"(addr))
#define MMA_FP16(d, a, b0, b1) \
    asm volatile("mma.sync.aligned.m16n8k16.row.col.f32.f16.f16.f32 " \
        "{%0,%1,%2,%3}, {%4,%5,%6,%7}, {%8,%9}, {%0,%1,%2,%3};" \
        : "+f"((d)[0]), "+f"((d)[1]), "+f"((d)[2]), "+f"((d)[3]) \
        : "r"((a)[0]), "r"((a)[1]), "r"((a)[2]), "r"((a)[3]), "r"(b0), "r"(b1))

__device__ __forceinline__ uint32_t packh2(float a, float b) {
    __half2 h = __floats2half2_rn(a, b);
    return *reinterpret_cast<uint32_t*>(&h);
}

// ---------------------------------------------------------------------------
// Fused conversion: x then [Wq|Wk|Wv|Wf], all hi-only fp16, float4-vectorized.
// ---------------------------------------------------------------------------
#define XV4 (M_ * WID_ / 4)
#define WV4 ((NQKV + WID_) * WID_ / 4)

__global__ __launch_bounds__(256)
void conv_all(const float4* __restrict__ x,
              const float4* __restrict__ Wq, const float4* __restrict__ Wk,
              const float4* __restrict__ Wv, const float4* __restrict__ Wf) {
    int idx = blockIdx.x * 256 + threadIdx.x;
    if (idx < XV4) {
        float4 v = x[idx];
        *(uint2*)&g_Xs[(size_t)idx * 4] =
            make_uint2(packh2(v.x, v.y), packh2(v.z, v.w));
        return;
    }
    int wi = idx - XV4;
    if (wi >= WV4) return;
    int r = wi >> 8, k4 = wi & 255;
    float4 v;
    __half* dst;
    if (r < 1024)      { v = Wq[wi];                       dst = g_Wqkvs; }
    else if (r < 1088) { v = Wk[(r - 1024) * 256 + k4];    dst = g_Wqkvs; }
    else if (r < NQKV) { v = Wv[(r - 1088) * 256 + k4];    dst = g_Wqkvs; }
    else               { v = Wf[(r - NQKV) * 256 + k4];    dst = g_Wfs; r -= NQKV; }
    *(uint2*)&dst[(size_t)r * KW_ + k4 * 4] =
        make_uint2(packh2(v.x, v.y), packh2(v.z, v.w));
}

// ---------------------------------------------------------------------------
// mma.sync fp16 GEMM: C[M,N] = A[M,1024] * B[N,1024]^T.
// CTA 128x128, 8 warps (4M x 2N). KC=32, 4-stage ring, ONE barrier/chunk
// (prefetch distance 2 on ring 4: writer never aliases a buffer a warp
// lagging at chunk c-1 may read).
// MODE 0: fp32 out + bias.  MODE 1: fused QKV epilogue (Q pre-scaled QSCALE).
// ---------------------------------------------------------------------------
#define KC 32
#define ROWT 80            // 32 halfs + 16B pad
#define STG 4
#define TBUF (128 * ROWT)  // 10240
#define GSMEM (STG * 2 * TBUF)   // 81920

template <int MODE>
__global__ __launch_bounds__(256, 2)
void gemm_mma(const __half* __restrict__ A, const __half* __restrict__ B,
              float* __restrict__ C, const float* __restrict__ bias, int N) {
    extern __shared__ __align__(16) char sm[];
    const uint32_t sA = smem_u32(sm);
    const uint32_t sB = sA + STG * TBUF;

    const int tid  = threadIdx.x;
    const int wid  = tid >> 5;
    const int lane = tid & 31;
    const int wm = (wid & 3) * 32;
    const int wn = (wid >> 2) * 64;
    const int bm = blockIdx.y;
    const int bn = blockIdx.x;

    const char* Ab = (const char*)(A + (size_t)bm * 128 * KW_);
    const char* Bb = (const char*)(B + (size_t)bn * 128 * KW_);

    float acc[2][8][4];
    #pragma unroll
    for (int i = 0; i < 2; i++)
        #pragma unroll
        for (int j = 0; j < 8; j++)
            #pragma unroll
            for (int q = 0; q < 4; q++) acc[i][j][q] = 0.f;

    const int nc = KW_ / KC;    // 32 chunks

    auto prefetch = [&](int ck) {
        const int buf = ck & (STG - 1);
        uint32_t as = sA + buf * TBUF;
        uint32_t bs = sB + buf * TBUF;
        const char* ag = Ab + ck * (KC * 2);
        const char* bg = Bb + ck * (KC * 2);
        #pragma unroll
        for (int t = 0; t < 2; t++) {
            int v = tid + t * 256;
            int row = v >> 2, c16 = (v & 3) * 16;
            CP_ASYNC16(as + row * ROWT + c16, ag + (size_t)row * 2048 + c16);
        }
        #pragma unroll
        for (int t = 0; t < 2; t++) {
            int v = tid + t * 256;
            int row = v >> 2, c16 = (v & 3) * 16;
            CP_ASYNC16(bs + row * ROWT + c16, bg + (size_t)row * 2048 + c16);
        }
    };

    prefetch(0); CP_COMMIT();
    prefetch(1); CP_COMMIT();

    const int a_r = lane & 15;
    const int a_c = (lane >> 4) * 16;
    const int b_r = (lane & 7) | ((lane >> 4) << 3);
    const int b_c = ((lane >> 3) & 1) * 16;

    for (int ck = 0; ck < nc; ck++) {
        if (ck + 2 < nc) { prefetch(ck + 2); CP_COMMIT(); CP_WAIT(2); }
        else if (ck + 1 < nc) CP_WAIT(1);
        else CP_WAIT(0);
        __syncthreads();

        const int buf = ck & (STG - 1);
        const uint32_t as = sA + buf * TBUF;
        const uint32_t bs = sB + buf * TBUF;

        #pragma unroll
        for (int ks = 0; ks < 2; ks++) {
            uint32_t af[2][4];
            #pragma unroll
            for (int mt = 0; mt < 2; mt++) {
                uint32_t base = as + (wm + mt * 16 + a_r) * ROWT + ks * 32 + a_c;
                LDSM_X4(af[mt][0], af[mt][1], af[mt][2], af[mt][3], base);
            }
            uint32_t bf2[4][4];
            #pragma unroll
            for (int nt = 0; nt < 4; nt++) {
                uint32_t addr = bs + (wn + nt * 16 + b_r) * ROWT + ks * 32 + b_c;
                LDSM_X4(bf2[nt][0], bf2[nt][1], bf2[nt][2], bf2[nt][3], addr);
            }
            #pragma unroll
            for (int mt = 0; mt < 2; mt++)
                #pragma unroll
                for (int n8 = 0; n8 < 8; n8++)
                    MMA_FP16(acc[mt][n8], af[mt],
                             bf2[n8 >> 1][(n8 & 1) * 2], bf2[n8 >> 1][(n8 & 1) * 2 + 1]);
        }
    }

    const int gid = lane >> 2;
    const int tig = lane & 3;
    #pragma unroll
    for (int mt = 0; mt < 2; mt++) {
        #pragma unroll
        for (int n8 = 0; n8 < 8; n8++) {
            int col  = bn * 128 + wn + n8 * 8 + tig * 2;
            int row0 = bm * 128 + wm + mt * 16 + gid;
            if (MODE == 0) {
                float bx = bias[col], by = bias[col + 1];
                float2 v0 = make_float2(acc[mt][n8][0] + bx, acc[mt][n8][1] + by);
                float2 v1 = make_float2(acc[mt][n8][2] + bx, acc[mt][n8][3] + by);
                *(float2*)&C[(size_t)row0 * N + col] = v0;
                *(float2*)&C[(size_t)(row0 + 8) * N + col] = v1;
            } else {
                #pragma unroll
                for (int rh = 0; rh < 2; rh++) {
                    int rr = row0 + rh * 8;
                    float va = acc[mt][n8][rh * 2], vb = acc[mt][n8][rh * 2 + 1];
                    if (col < 1024) {
                        *(uint32_t*)&g_Qh[(size_t)rr * WID_ + col] =
                            packh2(va * QSCALE, vb * QSCALE);
                    } else if (col < 1088) {
                        int d = col - 1024;
                        *(uint32_t*)&g_Ks[(size_t)rr * HD_ + d] = packh2(va, vb);
                    } else {
                        int d = col - 1088;
                        int bb = rr >> 11, t = rr & 2047;
                        g_Vt[((size_t)bb * 64 + d)     * 2048 + t] = __float2half_rn(va);
                        g_Vt[((size_t)bb * 64 + d + 1) * 2048 + t] = __float2half_rn(vb);
                    }
                }
            }
        }
    }
}

// ---------------------------------------------------------------------------
// FA2-style sliding-window attention, pure fp16 mma, 3-stage smem ring.
// CTA = 128 queries x 2 heads (16 warps). Softmax uses exp2 (scale folded
// into Q) and a single unsigned compare per element for the window mask.
// ---------------------------------------------------------------------------
#define KROW 144
#define VROW 144
#define KBUF (64 * KROW)
#define VBUF (64 * VROW)
#define CHBUF (KBUF + VBUF)
#define ASTG 3
#define NCH  6

__global__ __launch_bounds__(512)
void attn_mma(void) {
    extern __shared__ __align__(16) char sm[];
    const uint32_t sb = smem_u32(sm);

    const int tid  = threadIdx.x;
    const int wid  = tid >> 5;
    const int lane = tid & 31;
    const int gid  = lane >> 2;
    const int tig  = lane & 3;
    const int b    = blockIdx.z;
    const int q0   = blockIdx.x * 128;
    const int h    = blockIdx.y * 2 + (wid >> 3);
    const int qrow = q0 + (wid & 7) * 16;
    const int m0   = b * T_ + qrow;

    uint32_t qh[4][4];
    {
        const size_t r0 = (size_t)(m0 + gid) * WID_ + h * 64;
        const size_t r1 = (size_t)(m0 + gid + 8) * WID_ + h * 64;
        #pragma unroll
        for (int kt = 0; kt < 4; kt++) {
            int c = kt * 16 + tig * 2;
            qh[kt][0] = *(const uint32_t*)&g_Qh[r0 + c];
            qh[kt][1] = *(const uint32_t*)&g_Qh[r1 + c];
            qh[kt][2] = *(const uint32_t*)&g_Qh[r0 + c + 8];
            qh[kt][3] = *(const uint32_t*)&g_Qh[r1 + c + 8];
        }
    }

    float D[8][4];
    #pragma unroll
    for (int i = 0; i < 8; i++)
        #pragma unroll
        for (int j = 0; j < 4; j++) D[i][j] = 0.f;
    float l0 = 0.f, l1 = 0.f;

    const int c_start = (q0 >= WIN_) ? 0 : (WIN_ - q0) / 64;

    auto load_chunk = [&](int c) {
        const int kc = q0 - WIN_ + c * 64;
        const uint32_t kb = sb + (c % ASTG) * CHBUF;
        const uint32_t vb = kb + KBUF;
        {
            int row = tid >> 3, c16 = (tid & 7) * 16;
            CP_ASYNC16(kb + row * KROW + c16,
                       (const char*)g_Ks + ((size_t)(b * T_ + kc + row) * HD_) * 2 + c16);
        }
        {
            int d = tid >> 3, c16 = (tid & 7) * 16;
            CP_ASYNC16(vb + d * VROW + c16,
                       (const char*)g_Vt + ((size_t)(b * 64 + d) * 2048 + kc) * 2 + c16);
        }
    };

    load_chunk(c_start);
    CP_COMMIT();

    const int b_r = (lane & 7) | ((lane >> 4) << 3);
    const int b_c = ((lane >> 3) & 1) * 16;
    const int qp0 = qrow + gid;
    const int qp1 = qrow + gid + 8;

    for (int c = c_start; c < NCH; c++) {
        if (c < NCH - 1) { load_chunk(c + 1); CP_COMMIT(); CP_WAIT(1); }
        else             { CP_WAIT(0); }
        __syncthreads();

        const int kc = q0 - WIN_ + c * 64;
        const uint32_t kb = sb + (c % ASTG) * CHBUF;
        const uint32_t vb = kb + KBUF;
        // per-thread base deltas: valid iff 0 <= row - ka <= WIN_ (one unsigned cmp)
        const int d0 = qp0 - (kc + 2 * tig);   // row0 minus this thread's first key col
        const int d1 = qp1 - (kc + 2 * tig);

        float S[8][4];
        #pragma unroll
        for (int i = 0; i < 8; i++)
            #pragma unroll
            for (int j = 0; j < 4; j++) S[i][j] = 0.f;

        // ---- S = q * k (Q pre-scaled by log2e/8) ----
        #pragma unroll
        for (int kt = 0; kt < 4; kt++) {
            uint32_t bh[4][4];
            #pragma unroll
            for (int nt = 0; nt < 4; nt++)
                LDSM_X4(bh[nt][0], bh[nt][1], bh[nt][2], bh[nt][3],
                        kb + (nt * 16 + b_r) * KROW + kt * 32 + b_c);
            #pragma unroll
            for (int n8 = 0; n8 < 8; n8++)
                MMA_FP16(S[n8], qh[kt], bh[n8 >> 1][(n8 & 1) * 2], bh[n8 >> 1][(n8 & 1) * 2 + 1]);
        }

        // ---- softmax (exp2, no max shift) + PV ----
        #pragma unroll
        for (int s = 0; s < 4; s++) {
            uint32_t pa[4];
            #pragma unroll
            for (int half = 0; half < 2; half++) {
                int tile = 2 * s + half;
                float pe[4];
                #pragma unroll
                for (int e = 0; e < 4; e++) {
                    int dd  = ((e < 2) ? d0 : d1) - 8 * tile - (e & 1);
                    bool valid = (unsigned)dd <= (unsigned)WIN_;
                    pe[e] = valid ? exp2f(S[tile][e]) : 0.f;
                }
                l0 += pe[0] + pe[1];
                l1 += pe[2] + pe[3];
                pa[half * 2 + 0] = packh2(pe[0], pe[1]);
                pa[half * 2 + 1] = packh2(pe[2], pe[3]);
            }

            uint32_t bv[4][4];
            #pragma unroll
            for (int nt = 0; nt < 4; nt++)
                LDSM_X4(bv[nt][0], bv[nt][1], bv[nt][2], bv[nt][3],
                        vb + (nt * 16 + b_r) * VROW + s * 32 + b_c);
            #pragma unroll
            for (int dt = 0; dt < 8; dt++)
                MMA_FP16(D[dt], pa, bv[dt >> 1][(dt & 1) * 2], bv[dt >> 1][(dt & 1) * 2 + 1]);
        }
    }

    l0 += __shfl_xor_sync(0xFFFFFFFFu, l0, 1);
    l0 += __shfl_xor_sync(0xFFFFFFFFu, l0, 2);
    l1 += __shfl_xor_sync(0xFFFFFFFFu, l1, 1);
    l1 += __shfl_xor_sync(0xFFFFFFFFu, l1, 2);
    const float inv0 = 1.f / l0;
    const float inv1 = 1.f / l1;

    const size_t r0m = (size_t)(m0 + gid) * KW_;
    const size_t r1m = (size_t)(m0 + gid + 8) * KW_;
    #pragma unroll
    for (int dt = 0; dt < 8; dt++) {
        int col = h * 64 + dt * 8 + tig * 2;
        *(uint32_t*)&g_As[r0m + col] = packh2(D[dt][0] * inv0, D[dt][1] * inv0);
        *(uint32_t*)&g_As[r1m + col] = packh2(D[dt][2] * inv1, D[dt][3] * inv1);
    }
}

// ---------------------------------------------------------------------------
extern "C" void kernel_launch(void* const* d_in, const int* in_sizes, int n_in,
                              void* d_out, int out_size) {
    const float* x  = (const float*)d_in[0];
    const float* Wq = (const float*)d_in[2];
    const float* Wk = (const float*)d_in[3];
    const float* Wv = (const float*)d_in[4];
    const float* Wf = (const float*)d_in[5];
    const float* bf = (const float*)d_in[6];
    float* out = (float*)d_out;

    __half *Xs, *As, *Wqkvs, *Wfs;
    cudaGetSymbolAddress((void**)&Xs,    g_Xs);
    cudaGetSymbolAddress((void**)&As,    g_As);
    cudaGetSymbolAddress((void**)&Wqkvs, g_Wqkvs);
    cudaGetSymbolAddress((void**)&Wfs,   g_Wfs);

    static int init = 0;
    if (!init) {
        cudaFuncSetAttribute(attn_mma, cudaFuncAttributeMaxDynamicSharedMemorySize,
                             ASTG * CHBUF);
        cudaFuncSetAttribute((const void*)gemm_mma<1>,
                             cudaFuncAttributeMaxDynamicSharedMemorySize, GSMEM);
        cudaFuncSetAttribute((const void*)gemm_mma<0>,
                             cudaFuncAttributeMaxDynamicSharedMemorySize, GSMEM);
        init = 1;
    }

    // fused conversions (hi-only fp16)
    conv_all<<<(XV4 + WV4 + 255) / 256, 256>>>(
        (const float4*)x, (const float4*)Wq, (const float4*)Wk,
        (const float4*)Wv, (const float4*)Wf);

    // fused QKV projection (128x128 tiles, 288 CTAs)
    gemm_mma<1><<<dim3(NQKV / 128, M_ / 128), 256, GSMEM>>>(Xs, Wqkvs, nullptr, nullptr, NQKV);

    // attention (fp16 tensor cores, 128-query tiles)
    attn_mma<<<dim3(T_ / 128, NH_ / 2, B_), 512, ASTG * CHBUF>>>();

    // output projection (+bias, 256 CTAs)
    gemm_mma<0><<<dim3(WID_ / 128, M_ / 128), 256, GSMEM>>>(As, Wfs, out, bf, WID_);
}

// round 16
// speedup vs baseline: 1.0666x; 1.0111x over previous
#include <cuda_runtime.h>
#include <cuda_fp16.h>
#include <cstdint>

// ---------------------------------------------------------------------------
// LocalAttentionBlock on GB300 (sm_103 base PTX — no tcgen05):
//   GEMMs: plain fp16, 128x128 tiles, KC=64 chunks (16 barriers), STG=3 ring,
//   2 CTA/SM. Attention: FA2 fp16, 128-query x 2-head CTAs, exp2 softmax.
// b=2, t=2048, WIDTH=1024, HEADS=16, HEAD_DIM=64, WINDOW=256
// ---------------------------------------------------------------------------

#define B_    2
#define T_    2048
#define M_    (B_ * T_)        // 4096 rows
#define WID_  1024
#define NH_   16
#define HD_   64
#define WIN_  256
#define KW_   1024
#define NQKV  1152             // 1024 Q + 64 K + 64 V output cols

// Q prescale: (1/sqrt(64)) * log2(e), folded so softmax uses exp2 directly.
#define QSCALE 0.1803368801111191f

// ----- scratch (device globals; no allocations allowed) -----
__device__ __half g_Xs   [(size_t)M_ * KW_];
__device__ __half g_As   [(size_t)M_ * KW_];
__device__ __half g_Wqkvs[(size_t)NQKV * KW_];
__device__ __half g_Wfs  [(size_t)WID_ * KW_];
__device__ __half g_Qh   [(size_t)M_ * WID_];         // [m][h*64+d], pre-scaled
__device__ __half g_Ks   [(size_t)M_ * HD_];          // [m][d]
__device__ __half g_Vt   [(size_t)B_ * HD_ * T_];     // [b][d][t]

// ---------------------------------------------------------------------------
__device__ __forceinline__ uint32_t smem_u32(const void* p) {
    uint32_t a;
    asm("{ .reg .u64 t; cvta.to.shared.u64 t, %1; cvt.u32.u64 %0, t; }"
        : "=r"(a) : "l"(p));
    return a;
}
#define CP_ASYNC16(dst, src) \
    asm volatile("cp.async.cg.shared.global [%0], [%1], 16;" \
        :: "r"(dst), "l"(src) : "memory")
#define CP_COMMIT() asm volatile("cp.async.commit_group;" ::: "memory")
#define CP_WAIT(n)  asm volatile("cp.async.wait_group %0;" :: "n"(n) : "memory")
#define LDSM_X4(r0, r1, r2, r3, addr) \
    asm volatile("ldmatrix.sync.aligned.m8n8.x4.shared.b16 {%0,%1,%2,%3}, [%4];" \
        : "=r"(r0), "=r"(r1), "=r"(r2), "=r"(r3) : "r"(addr))
#define MMA_FP16(d, a, b0, b1) \
    asm volatile("mma.sync.aligned.m16n8k16.row.col.f32.f16.f16.f32 " \
        "{%0,%1,%2,%3}, {%4,%5,%6,%7}, {%8,%9}, {%0,%1,%2,%3};" \
        : "+f"((d)[0]), "+f"((d)[1]), "+f"((d)[2]), "+f"((d)[3]) \
        : "r"((a)[0]), "r"((a)[1]), "r"((a)[2]), "r"((a)[3]), "r"(b0), "r"(b1))

__device__ __forceinline__ uint32_t packh2(float a, float b) {
    __half2 h = __floats2half2_rn(a, b);
    return *reinterpret_cast<uint32_t*>(&h);
}

// ---------------------------------------------------------------------------
// Fused conversion: x then [Wq|Wk|Wv|Wf], all hi-only fp16, float4-vectorized.
// ---------------------------------------------------------------------------
#define XV4 (M_ * WID_ / 4)
#define WV4 ((NQKV + WID_) * WID_ / 4)

__global__ __launch_bounds__(256)
void conv_all(const float4* __restrict__ x,
              const float4* __restrict__ Wq, const float4* __restrict__ Wk,
              const float4* __restrict__ Wv, const float4* __restrict__ Wf) {
    int idx = blockIdx.x * 256 + threadIdx.x;
    if (idx < XV4) {
        float4 v = x[idx];
        *(uint2*)&g_Xs[(size_t)idx * 4] =
            make_uint2(packh2(v.x, v.y), packh2(v.z, v.w));
        return;
    }
    int wi = idx - XV4;
    if (wi >= WV4) return;
    int r = wi >> 8, k4 = wi & 255;
    float4 v;
    __half* dst;
    if (r < 1024)      { v = Wq[wi];                       dst = g_Wqkvs; }
    else if (r < 1088) { v = Wk[(r - 1024) * 256 + k4];    dst = g_Wqkvs; }
    else if (r < NQKV) { v = Wv[(r - 1088) * 256 + k4];    dst = g_Wqkvs; }
    else               { v = Wf[(r - NQKV) * 256 + k4];    dst = g_Wfs; r -= NQKV; }
    *(uint2*)&dst[(size_t)r * KW_ + k4 * 4] =
        make_uint2(packh2(v.x, v.y), packh2(v.z, v.w));
}

// ---------------------------------------------------------------------------
// mma.sync fp16 GEMM: C[M,N] = A[M,1024] * B[N,1024]^T.
// CTA 128x128, 8 warps (4M x 2N). KC=64 (16 chunks), STG=3 ring, ONE
// barrier/chunk. Prefetch distance 2, issued AFTER the barrier: no warp can
// still read chunk c-1 there, and (c+2)%3 != c%3 -> race-free; wait(1) at
// loop top guarantees buffer c complete.
// MODE 0: fp32 out + bias.  MODE 1: fused QKV epilogue (Q pre-scaled QSCALE).
// ---------------------------------------------------------------------------
#define KC 64
#define ROWT 144           // 64 halfs (128B) + 16B pad; 8-row bank stride 4
#define STG 3
#define TBUF (128 * ROWT)  // 18432
#define GSMEM (STG * 2 * TBUF)   // 110592

template <int MODE>
__global__ __launch_bounds__(256, 2)
void gemm_mma(const __half* __restrict__ A, const __half* __restrict__ B,
              float* __restrict__ C, const float* __restrict__ bias, int N) {
    extern __shared__ __align__(16) char sm[];
    const uint32_t sA = smem_u32(sm);
    const uint32_t sB = sA + STG * TBUF;

    const int tid  = threadIdx.x;
    const int wid  = tid >> 5;
    const int lane = tid & 31;
    const int wm = (wid & 3) * 32;
    const int wn = (wid >> 2) * 64;
    const int bm = blockIdx.y;
    const int bn = blockIdx.x;

    const char* Ab = (const char*)(A + (size_t)bm * 128 * KW_);
    const char* Bb = (const char*)(B + (size_t)bn * 128 * KW_);

    float acc[2][8][4];
    #pragma unroll
    for (int i = 0; i < 2; i++)
        #pragma unroll
        for (int j = 0; j < 8; j++)
            #pragma unroll
            for (int q = 0; q < 4; q++) acc[i][j][q] = 0.f;

    const int nc = KW_ / KC;    // 16 chunks

    auto prefetch = [&](int ck) {
        const int buf = ck % STG;
        uint32_t as = sA + buf * TBUF;
        uint32_t bs = sB + buf * TBUF;
        const char* ag = Ab + ck * (KC * 2);
        const char* bg = Bb + ck * (KC * 2);
        // 128 rows x 8 vec16 per operand = 1024 vecs, 4/thread each
        #pragma unroll
        for (int t = 0; t < 4; t++) {
            int v = tid + t * 256;
            int row = v >> 3, c16 = (v & 7) * 16;
            CP_ASYNC16(as + row * ROWT + c16, ag + (size_t)row * 2048 + c16);
        }
        #pragma unroll
        for (int t = 0; t < 4; t++) {
            int v = tid + t * 256;
            int row = v >> 3, c16 = (v & 7) * 16;
            CP_ASYNC16(bs + row * ROWT + c16, bg + (size_t)row * 2048 + c16);
        }
    };

    prefetch(0); CP_COMMIT();
    prefetch(1); CP_COMMIT();

    const int a_r = lane & 15;
    const int a_c = (lane >> 4) * 16;
    const int b_r = (lane & 7) | ((lane >> 4) << 3);
    const int b_c = ((lane >> 3) & 1) * 16;

    for (int ck = 0; ck < nc; ck++) {
        if (ck + 1 < nc) CP_WAIT(1); else CP_WAIT(0);
        __syncthreads();
        if (ck + 2 < nc) { prefetch(ck + 2); CP_COMMIT(); }

        const int buf = ck % STG;
        const uint32_t as = sA + buf * TBUF;
        const uint32_t bs = sB + buf * TBUF;

        #pragma unroll
        for (int ks = 0; ks < 4; ks++) {
            uint32_t af[2][4];
            #pragma unroll
            for (int mt = 0; mt < 2; mt++) {
                uint32_t base = as + (wm + mt * 16 + a_r) * ROWT + ks * 32 + a_c;
                LDSM_X4(af[mt][0], af[mt][1], af[mt][2], af[mt][3], base);
            }
            uint32_t bf2[4][4];
            #pragma unroll
            for (int nt = 0; nt < 4; nt++) {
                uint32_t addr = bs + (wn + nt * 16 + b_r) * ROWT + ks * 32 + b_c;
                LDSM_X4(bf2[nt][0], bf2[nt][1], bf2[nt][2], bf2[nt][3], addr);
            }
            #pragma unroll
            for (int mt = 0; mt < 2; mt++)
                #pragma unroll
                for (int n8 = 0; n8 < 8; n8++)
                    MMA_FP16(acc[mt][n8], af[mt],
                             bf2[n8 >> 1][(n8 & 1) * 2], bf2[n8 >> 1][(n8 & 1) * 2 + 1]);
        }
    }

    const int gid = lane >> 2;
    const int tig = lane & 3;
    #pragma unroll
    for (int mt = 0; mt < 2; mt++) {
        #pragma unroll
        for (int n8 = 0; n8 < 8; n8++) {
            int col  = bn * 128 + wn + n8 * 8 + tig * 2;
            int row0 = bm * 128 + wm + mt * 16 + gid;
            if (MODE == 0) {
                float bx = bias[col], by = bias[col + 1];
                float2 v0 = make_float2(acc[mt][n8][0] + bx, acc[mt][n8][1] + by);
                float2 v1 = make_float2(acc[mt][n8][2] + bx, acc[mt][n8][3] + by);
                *(float2*)&C[(size_t)row0 * N + col] = v0;
                *(float2*)&C[(size_t)(row0 + 8) * N + col] = v1;
            } else {
                #pragma unroll
                for (int rh = 0; rh < 2; rh++) {
                    int rr = row0 + rh * 8;
                    float va = acc[mt][n8][rh * 2], vb = acc[mt][n8][rh * 2 + 1];
                    if (col < 1024) {
                        *(uint32_t*)&g_Qh[(size_t)rr * WID_ + col] =
                            packh2(va * QSCALE, vb * QSCALE);
                    } else if (col < 1088) {
                        int d = col - 1024;
                        *(uint32_t*)&g_Ks[(size_t)rr * HD_ + d] = packh2(va, vb);
                    } else {
                        int d = col - 1088;
                        int bb = rr >> 11, t = rr & 2047;
                        g_Vt[((size_t)bb * 64 + d)     * 2048 + t] = __float2half_rn(va);
                        g_Vt[((size_t)bb * 64 + d + 1) * 2048 + t] = __float2half_rn(vb);
                    }
                }
            }
        }
    }
}

// ---------------------------------------------------------------------------
// FA2-style sliding-window attention, pure fp16 mma, 3-stage smem ring.
// CTA = 128 queries x 2 heads (16 warps); exp2 softmax, 1-compare masks.
// ---------------------------------------------------------------------------
#define KROW 144
#define VROW 144
#define KBUF (64 * KROW)
#define VBUF (64 * VROW)
#define CHBUF (KBUF + VBUF)
#define ASTG 3
#define NCH  6

__global__ __launch_bounds__(512)
void attn_mma(void) {
    extern __shared__ __align__(16) char sm[];
    const uint32_t sb = smem_u32(sm);

    const int tid  = threadIdx.x;
    const int wid  = tid >> 5;
    const int lane = tid & 31;
    const int gid  = lane >> 2;
    const int tig  = lane & 3;
    const int b    = blockIdx.z;
    const int q0   = blockIdx.x * 128;
    const int h    = blockIdx.y * 2 + (wid >> 3);
    const int qrow = q0 + (wid & 7) * 16;
    const int m0   = b * T_ + qrow;

    uint32_t qh[4][4];
    {
        const size_t r0 = (size_t)(m0 + gid) * WID_ + h * 64;
        const size_t r1 = (size_t)(m0 + gid + 8) * WID_ + h * 64;
        #pragma unroll
        for (int kt = 0; kt < 4; kt++) {
            int c = kt * 16 + tig * 2;
            qh[kt][0] = *(const uint32_t*)&g_Qh[r0 + c];
            qh[kt][1] = *(const uint32_t*)&g_Qh[r1 + c];
            qh[kt][2] = *(const uint32_t*)&g_Qh[r0 + c + 8];
            qh[kt][3] = *(const uint32_t*)&g_Qh[r1 + c + 8];
        }
    }

    float D[8][4];
    #pragma unroll
    for (int i = 0; i < 8; i++)
        #pragma unroll
        for (int j = 0; j < 4; j++) D[i][j] = 0.f;
    float l0 = 0.f, l1 = 0.f;

    const int c_start = (q0 >= WIN_) ? 0 : (WIN_ - q0) / 64;

    auto load_chunk = [&](int c) {
        const int kc = q0 - WIN_ + c * 64;
        const uint32_t kb = sb + (c % ASTG) * CHBUF;
        const uint32_t vb = kb + KBUF;
        {
            int row = tid >> 3, c16 = (tid & 7) * 16;
            CP_ASYNC16(kb + row * KROW + c16,
                       (const char*)g_Ks + ((size_t)(b * T_ + kc + row) * HD_) * 2 + c16);
        }
        {
            int d = tid >> 3, c16 = (tid & 7) * 16;
            CP_ASYNC16(vb + d * VROW + c16,
                       (const char*)g_Vt + ((size_t)(b * 64 + d) * 2048 + kc) * 2 + c16);
        }
    };

    load_chunk(c_start);
    CP_COMMIT();

    const int b_r = (lane & 7) | ((lane >> 4) << 3);
    const int b_c = ((lane >> 3) & 1) * 16;
    const int qp0 = qrow + gid;
    const int qp1 = qrow + gid + 8;

    for (int c = c_start; c < NCH; c++) {
        if (c < NCH - 1) { load_chunk(c + 1); CP_COMMIT(); CP_WAIT(1); }
        else             { CP_WAIT(0); }
        __syncthreads();

        const int kc = q0 - WIN_ + c * 64;
        const uint32_t kb = sb + (c % ASTG) * CHBUF;
        const uint32_t vb = kb + KBUF;
        const int d0 = qp0 - (kc + 2 * tig);
        const int d1 = qp1 - (kc + 2 * tig);

        float S[8][4];
        #pragma unroll
        for (int i = 0; i < 8; i++)
            #pragma unroll
            for (int j = 0; j < 4; j++) S[i][j] = 0.f;

        #pragma unroll
        for (int kt = 0; kt < 4; kt++) {
            uint32_t bh[4][4];
            #pragma unroll
            for (int nt = 0; nt < 4; nt++)
                LDSM_X4(bh[nt][0], bh[nt][1], bh[nt][2], bh[nt][3],
                        kb + (nt * 16 + b_r) * KROW + kt * 32 + b_c);
            #pragma unroll
            for (int n8 = 0; n8 < 8; n8++)
                MMA_FP16(S[n8], qh[kt], bh[n8 >> 1][(n8 & 1) * 2], bh[n8 >> 1][(n8 & 1) * 2 + 1]);
        }

        #pragma unroll
        for (int s = 0; s < 4; s++) {
            uint32_t pa[4];
            #pragma unroll
            for (int half = 0; half < 2; half++) {
                int tile = 2 * s + half;
                float pe[4];
                #pragma unroll
                for (int e = 0; e < 4; e++) {
                    int dd  = ((e < 2) ? d0 : d1) - 8 * tile - (e & 1);
                    bool valid = (unsigned)dd <= (unsigned)WIN_;
                    pe[e] = valid ? exp2f(S[tile][e]) : 0.f;
                }
                l0 += pe[0] + pe[1];
                l1 += pe[2] + pe[3];
                pa[half * 2 + 0] = packh2(pe[0], pe[1]);
                pa[half * 2 + 1] = packh2(pe[2], pe[3]);
            }

            uint32_t bv[4][4];
            #pragma unroll
            for (int nt = 0; nt < 4; nt++)
                LDSM_X4(bv[nt][0], bv[nt][1], bv[nt][2], bv[nt][3],
                        vb + (nt * 16 + b_r) * VROW + s * 32 + b_c);
            #pragma unroll
            for (int dt = 0; dt < 8; dt++)
                MMA_FP16(D[dt], pa, bv[dt >> 1][(dt & 1) * 2], bv[dt >> 1][(dt & 1) * 2 + 1]);
        }
    }

    l0 += __shfl_xor_sync(0xFFFFFFFFu, l0, 1);
    l0 += __shfl_xor_sync(0xFFFFFFFFu, l0, 2);
    l1 += __shfl_xor_sync(0xFFFFFFFFu, l1, 1);
    l1 += __shfl_xor_sync(0xFFFFFFFFu, l1, 2);
    const float inv0 = 1.f / l0;
    const float inv1 = 1.f / l1;

    const size_t r0m = (size_t)(m0 + gid) * KW_;
    const size_t r1m = (size_t)(m0 + gid + 8) * KW_;
    #pragma unroll
    for (int dt = 0; dt < 8; dt++) {
        int col = h * 64 + dt * 8 + tig * 2;
        *(uint32_t*)&g_As[r0m + col] = packh2(D[dt][0] * inv0, D[dt][1] * inv0);
        *(uint32_t*)&g_As[r1m + col] = packh2(D[dt][2] * inv1, D[dt][3] * inv1);
    }
}

// ---------------------------------------------------------------------------
extern "C" void kernel_launch(void* const* d_in, const int* in_sizes, int n_in,
                              void* d_out, int out_size) {
    const float* x  = (const float*)d_in[0];
    const float* Wq = (const float*)d_in[2];
    const float* Wk = (const float*)d_in[3];
    const float* Wv = (const float*)d_in[4];
    const float* Wf = (const float*)d_in[5];
    const float* bf = (const float*)d_in[6];
    float* out = (float*)d_out;

    __half *Xs, *As, *Wqkvs, *Wfs;
    cudaGetSymbolAddress((void**)&Xs,    g_Xs);
    cudaGetSymbolAddress((void**)&As,    g_As);
    cudaGetSymbolAddress((void**)&Wqkvs, g_Wqkvs);
    cudaGetSymbolAddress((void**)&Wfs,   g_Wfs);

    static int init = 0;
    if (!init) {
        cudaFuncSetAttribute(attn_mma, cudaFuncAttributeMaxDynamicSharedMemorySize,
                             ASTG * CHBUF);
        cudaFuncSetAttribute((const void*)gemm_mma<1>,
                             cudaFuncAttributeMaxDynamicSharedMemorySize, GSMEM);
        cudaFuncSetAttribute((const void*)gemm_mma<0>,
                             cudaFuncAttributeMaxDynamicSharedMemorySize, GSMEM);
        init = 1;
    }

    // fused conversions (hi-only fp16)
    conv_all<<<(XV4 + WV4 + 255) / 256, 256>>>(
        (const float4*)x, (const float4*)Wq, (const float4*)Wk,
        (const float4*)Wv, (const float4*)Wf);

    // fused QKV projection (128x128 tiles, 288 CTAs)
    gemm_mma<1><<<dim3(NQKV / 128, M_ / 128), 256, GSMEM>>>(Xs, Wqkvs, nullptr, nullptr, NQKV);

    // attention (fp16 tensor cores, 128-query tiles)
    attn_mma<<<dim3(T_ / 128, NH_ / 2, B_), 512, ASTG * CHBUF>>>();

    // output projection (+bias, 256 CTAs)
    gemm_mma<0><<<dim3(WID_ / 128, M_ / 128), 256, GSMEM>>>(As, Wfs, out, bf, WID_);
}

// round 17
// speedup vs baseline: 1.1021x; 1.0333x over previous
#include <cuda_runtime.h>
#include <cuda_fp16.h>
#include <cstdint>

// ---------------------------------------------------------------------------
// LocalAttentionBlock on GB300 (sm_103 base PTX — no tcgen05):
//   GEMMs: plain fp16, 128x128 tiles, KC=64 chunks, STG=3 ring, 2 CTA/SM
//   (at the legacy-HMMA issue floor). Attention: FA2 fp16, 128-query x
//   2-head CTAs, per-warp chunk skipping (warps compute 5 of 6 chunks).
// b=2, t=2048, WIDTH=1024, HEADS=16, HEAD_DIM=64, WINDOW=256
// ---------------------------------------------------------------------------

#define B_    2
#define T_    2048
#define M_    (B_ * T_)        // 4096 rows
#define WID_  1024
#define NH_   16
#define HD_   64
#define WIN_  256
#define KW_   1024
#define NQKV  1152             // 1024 Q + 64 K + 64 V output cols

// Q prescale: (1/sqrt(64)) * log2(e), folded so softmax uses exp2 directly.
#define QSCALE 0.1803368801111191f

// ----- scratch (device globals; no allocations allowed) -----
__device__ __half g_Xs   [(size_t)M_ * KW_];
__device__ __half g_As   [(size_t)M_ * KW_];
__device__ __half g_Wqkvs[(size_t)NQKV * KW_];
__device__ __half g_Wfs  [(size_t)WID_ * KW_];
__device__ __half g_Qh   [(size_t)M_ * WID_];         // [m][h*64+d], pre-scaled
__device__ __half g_Ks   [(size_t)M_ * HD_];          // [m][d]
__device__ __half g_Vt   [(size_t)B_ * HD_ * T_];     // [b][d][t]

// ---------------------------------------------------------------------------
__device__ __forceinline__ uint32_t smem_u32(const void* p) {
    uint32_t a;
    asm("{ .reg .u64 t; cvta.to.shared.u64 t, %1; cvt.u32.u64 %0, t; }"
        : "=r"(a) : "l"(p));
    return a;
}
#define CP_ASYNC16(dst, src) \
    asm volatile("cp.async.cg.shared.global [%0], [%1], 16;" \
        :: "r"(dst), "l"(src) : "memory")
#define CP_COMMIT() asm volatile("cp.async.commit_group;" ::: "memory")
#define CP_WAIT(n)  asm volatile("cp.async.wait_group %0;" :: "n"(n) : "memory")
#define LDSM_X4(r0, r1, r2, r3, addr) \
    asm volatile("ldmatrix.sync.aligned.m8n8.x4.shared.b16 {%0,%1,%2,%3}, [%4];" \
        : "=r"(r0), "=r"(r1), "=r"(r2), "=r"(r3) : "r"(addr))
#define MMA_FP16(d, a, b0, b1) \
    asm volatile("mma.sync.aligned.m16n8k16.row.col.f32.f16.f16.f32 " \
        "{%0,%1,%2,%3}, {%4,%5,%6,%7}, {%8,%9}, {%0,%1,%2,%3};" \
        : "+f"((d)[0]), "+f"((d)[1]), "+f"((d)[2]), "+f"((d)[3]) \
        : "r"((a)[0]), "r"((a)[1]), "r"((a)[2]), "r"((a)[3]), "r"(b0), "r"(b1))

__device__ __forceinline__ uint32_t packh2(float a, float b) {
    __half2 h = __floats2half2_rn(a, b);
    return *reinterpret_cast<uint32_t*>(&h);
}

// ---------------------------------------------------------------------------
// Fused conversion: x then [Wq|Wk|Wv|Wf], all hi-only fp16, float4-vectorized.
// ---------------------------------------------------------------------------
#define XV4 (M_ * WID_ / 4)
#define WV4 ((NQKV + WID_) * WID_ / 4)

__global__ __launch_bounds__(256)
void conv_all(const float4* __restrict__ x,
              const float4* __restrict__ Wq, const float4* __restrict__ Wk,
              const float4* __restrict__ Wv, const float4* __restrict__ Wf) {
    int idx = blockIdx.x * 256 + threadIdx.x;
    if (idx < XV4) {
        float4 v = x[idx];
        *(uint2*)&g_Xs[(size_t)idx * 4] =
            make_uint2(packh2(v.x, v.y), packh2(v.z, v.w));
        return;
    }
    int wi = idx - XV4;
    if (wi >= WV4) return;
    int r = wi >> 8, k4 = wi & 255;
    float4 v;
    __half* dst;
    if (r < 1024)      { v = Wq[wi];                       dst = g_Wqkvs; }
    else if (r < 1088) { v = Wk[(r - 1024) * 256 + k4];    dst = g_Wqkvs; }
    else if (r < NQKV) { v = Wv[(r - 1088) * 256 + k4];    dst = g_Wqkvs; }
    else               { v = Wf[(r - NQKV) * 256 + k4];    dst = g_Wfs; r -= NQKV; }
    *(uint2*)&dst[(size_t)r * KW_ + k4 * 4] =
        make_uint2(packh2(v.x, v.y), packh2(v.z, v.w));
}

// ---------------------------------------------------------------------------
// mma.sync fp16 GEMM: C[M,N] = A[M,1024] * B[N,1024]^T.
// CTA 128x128, 8 warps (4M x 2N). KC=64 (16 chunks), STG=3 ring, ONE
// barrier/chunk (prefetch distance 2 issued after the barrier; (c+2)%3 != c%3).
// MODE 0: fp32 out + bias.  MODE 1: fused QKV epilogue (Q pre-scaled QSCALE).
// ---------------------------------------------------------------------------
#define KC 64
#define ROWT 144           // 64 halfs (128B) + 16B pad
#define STG 3
#define TBUF (128 * ROWT)  // 18432
#define GSMEM (STG * 2 * TBUF)   // 110592

template <int MODE>
__global__ __launch_bounds__(256, 2)
void gemm_mma(const __half* __restrict__ A, const __half* __restrict__ B,
              float* __restrict__ C, const float* __restrict__ bias, int N) {
    extern __shared__ __align__(16) char sm[];
    const uint32_t sA = smem_u32(sm);
    const uint32_t sB = sA + STG * TBUF;

    const int tid  = threadIdx.x;
    const int wid  = tid >> 5;
    const int lane = tid & 31;
    const int wm = (wid & 3) * 32;
    const int wn = (wid >> 2) * 64;
    const int bm = blockIdx.y;
    const int bn = blockIdx.x;

    const char* Ab = (const char*)(A + (size_t)bm * 128 * KW_);
    const char* Bb = (const char*)(B + (size_t)bn * 128 * KW_);

    float acc[2][8][4];
    #pragma unroll
    for (int i = 0; i < 2; i++)
        #pragma unroll
        for (int j = 0; j < 8; j++)
            #pragma unroll
            for (int q = 0; q < 4; q++) acc[i][j][q] = 0.f;

    const int nc = KW_ / KC;    // 16 chunks

    auto prefetch = [&](int ck) {
        const int buf = ck % STG;
        uint32_t as = sA + buf * TBUF;
        uint32_t bs = sB + buf * TBUF;
        const char* ag = Ab + ck * (KC * 2);
        const char* bg = Bb + ck * (KC * 2);
        #pragma unroll
        for (int t = 0; t < 4; t++) {
            int v = tid + t * 256;
            int row = v >> 3, c16 = (v & 7) * 16;
            CP_ASYNC16(as + row * ROWT + c16, ag + (size_t)row * 2048 + c16);
        }
        #pragma unroll
        for (int t = 0; t < 4; t++) {
            int v = tid + t * 256;
            int row = v >> 3, c16 = (v & 7) * 16;
            CP_ASYNC16(bs + row * ROWT + c16, bg + (size_t)row * 2048 + c16);
        }
    };

    prefetch(0); CP_COMMIT();
    prefetch(1); CP_COMMIT();

    const int a_r = lane & 15;
    const int a_c = (lane >> 4) * 16;
    const int b_r = (lane & 7) | ((lane >> 4) << 3);
    const int b_c = ((lane >> 3) & 1) * 16;

    for (int ck = 0; ck < nc; ck++) {
        if (ck + 1 < nc) CP_WAIT(1); else CP_WAIT(0);
        __syncthreads();
        if (ck + 2 < nc) { prefetch(ck + 2); CP_COMMIT(); }

        const int buf = ck % STG;
        const uint32_t as = sA + buf * TBUF;
        const uint32_t bs = sB + buf * TBUF;

        #pragma unroll
        for (int ks = 0; ks < 4; ks++) {
            uint32_t af[2][4];
            #pragma unroll
            for (int mt = 0; mt < 2; mt++) {
                uint32_t base = as + (wm + mt * 16 + a_r) * ROWT + ks * 32 + a_c;
                LDSM_X4(af[mt][0], af[mt][1], af[mt][2], af[mt][3], base);
            }
            uint32_t bf2[4][4];
            #pragma unroll
            for (int nt = 0; nt < 4; nt++) {
                uint32_t addr = bs + (wn + nt * 16 + b_r) * ROWT + ks * 32 + b_c;
                LDSM_X4(bf2[nt][0], bf2[nt][1], bf2[nt][2], bf2[nt][3], addr);
            }
            #pragma unroll
            for (int mt = 0; mt < 2; mt++)
                #pragma unroll
                for (int n8 = 0; n8 < 8; n8++)
                    MMA_FP16(acc[mt][n8], af[mt],
                             bf2[n8 >> 1][(n8 & 1) * 2], bf2[n8 >> 1][(n8 & 1) * 2 + 1]);
        }
    }

    const int gid = lane >> 2;
    const int tig = lane & 3;
    #pragma unroll
    for (int mt = 0; mt < 2; mt++) {
        #pragma unroll
        for (int n8 = 0; n8 < 8; n8++) {
            int col  = bn * 128 + wn + n8 * 8 + tig * 2;
            int row0 = bm * 128 + wm + mt * 16 + gid;
            if (MODE == 0) {
                float bx = bias[col], by = bias[col + 1];
                float2 v0 = make_float2(acc[mt][n8][0] + bx, acc[mt][n8][1] + by);
                float2 v1 = make_float2(acc[mt][n8][2] + bx, acc[mt][n8][3] + by);
                *(float2*)&C[(size_t)row0 * N + col] = v0;
                *(float2*)&C[(size_t)(row0 + 8) * N + col] = v1;
            } else {
                #pragma unroll
                for (int rh = 0; rh < 2; rh++) {
                    int rr = row0 + rh * 8;
                    float va = acc[mt][n8][rh * 2], vb = acc[mt][n8][rh * 2 + 1];
                    if (col < 1024) {
                        *(uint32_t*)&g_Qh[(size_t)rr * WID_ + col] =
                            packh2(va * QSCALE, vb * QSCALE);
                    } else if (col < 1088) {
                        int d = col - 1024;
                        *(uint32_t*)&g_Ks[(size_t)rr * HD_ + d] = packh2(va, vb);
                    } else {
                        int d = col - 1088;
                        int bb = rr >> 11, t = rr & 2047;
                        g_Vt[((size_t)bb * 64 + d)     * 2048 + t] = __float2half_rn(va);
                        g_Vt[((size_t)bb * 64 + d + 1) * 2048 + t] = __float2half_rn(vb);
                    }
                }
            }
        }
    }
}

// ---------------------------------------------------------------------------
// FA2-style sliding-window attention, pure fp16 mma, 3-stage smem ring.
// CTA = 128 queries x 2 heads (16 warps). Per-warp chunk skip: warp at
// m-offset w has valid keys only in [qrow-256, qrow+15], so warps 0-3 skip
// chunk 5 and warps 4-7 skip chunk 0 (those chunks were fully masked ->
// output bit-identical). Barriers and loads remain CTA-uniform.
// ---------------------------------------------------------------------------
#define KROW 144
#define VROW 144
#define KBUF (64 * KROW)
#define VBUF (64 * VROW)
#define CHBUF (KBUF + VBUF)
#define ASTG 3
#define NCH  6

__global__ __launch_bounds__(512)
void attn_mma(void) {
    extern __shared__ __align__(16) char sm[];
    const uint32_t sb = smem_u32(sm);

    const int tid  = threadIdx.x;
    const int wid  = tid >> 5;
    const int lane = tid & 31;
    const int gid  = lane >> 2;
    const int tig  = lane & 3;
    const int b    = blockIdx.z;
    const int q0   = blockIdx.x * 128;
    const int h    = blockIdx.y * 2 + (wid >> 3);
    const int wq   = wid & 7;            // m-warp index within q-tile
    const int qrow = q0 + wq * 16;
    const int m0   = b * T_ + qrow;

    // chunks this warp actually needs: [wlo, whi] (5 of the 6)
    const int wlo = (wq >= 4) ? 1 : 0;
    const int whi = (wq >= 4) ? 5 : 4;

    uint32_t qh[4][4];
    {
        const size_t r0 = (size_t)(m0 + gid) * WID_ + h * 64;
        const size_t r1 = (size_t)(m0 + gid + 8) * WID_ + h * 64;
        #pragma unroll
        for (int kt = 0; kt < 4; kt++) {
            int c = kt * 16 + tig * 2;
            qh[kt][0] = *(const uint32_t*)&g_Qh[r0 + c];
            qh[kt][1] = *(const uint32_t*)&g_Qh[r1 + c];
            qh[kt][2] = *(const uint32_t*)&g_Qh[r0 + c + 8];
            qh[kt][3] = *(const uint32_t*)&g_Qh[r1 + c + 8];
        }
    }

    float D[8][4];
    #pragma unroll
    for (int i = 0; i < 8; i++)
        #pragma unroll
        for (int j = 0; j < 4; j++) D[i][j] = 0.f;
    float l0 = 0.f, l1 = 0.f;

    const int c_start = (q0 >= WIN_) ? 0 : (WIN_ - q0) / 64;

    auto load_chunk = [&](int c) {
        const int kc = q0 - WIN_ + c * 64;
        const uint32_t kb = sb + (c % ASTG) * CHBUF;
        const uint32_t vb = kb + KBUF;
        {
            int row = tid >> 3, c16 = (tid & 7) * 16;
            CP_ASYNC16(kb + row * KROW + c16,
                       (const char*)g_Ks + ((size_t)(b * T_ + kc + row) * HD_) * 2 + c16);
        }
        {
            int d = tid >> 3, c16 = (tid & 7) * 16;
            CP_ASYNC16(vb + d * VROW + c16,
                       (const char*)g_Vt + ((size_t)(b * 64 + d) * 2048 + kc) * 2 + c16);
        }
    };

    load_chunk(c_start);
    CP_COMMIT();

    const int b_r = (lane & 7) | ((lane >> 4) << 3);
    const int b_c = ((lane >> 3) & 1) * 16;
    const int qp0 = qrow + gid;
    const int qp1 = qrow + gid + 8;

    for (int c = c_start; c < NCH; c++) {
        if (c < NCH - 1) { load_chunk(c + 1); CP_COMMIT(); CP_WAIT(1); }
        else             { CP_WAIT(0); }
        __syncthreads();

        if (c >= wlo && c <= whi) {
            const int kc = q0 - WIN_ + c * 64;
            const uint32_t kb = sb + (c % ASTG) * CHBUF;
            const uint32_t vb = kb + KBUF;
            const int d0 = qp0 - (kc + 2 * tig);
            const int d1 = qp1 - (kc + 2 * tig);

            float S[8][4];
            #pragma unroll
            for (int i = 0; i < 8; i++)
                #pragma unroll
                for (int j = 0; j < 4; j++) S[i][j] = 0.f;

            #pragma unroll
            for (int kt = 0; kt < 4; kt++) {
                uint32_t bh[4][4];
                #pragma unroll
                for (int nt = 0; nt < 4; nt++)
                    LDSM_X4(bh[nt][0], bh[nt][1], bh[nt][2], bh[nt][3],
                            kb + (nt * 16 + b_r) * KROW + kt * 32 + b_c);
                #pragma unroll
                for (int n8 = 0; n8 < 8; n8++)
                    MMA_FP16(S[n8], qh[kt], bh[n8 >> 1][(n8 & 1) * 2],
                             bh[n8 >> 1][(n8 & 1) * 2 + 1]);
            }

            #pragma unroll
            for (int s = 0; s < 4; s++) {
                uint32_t pa[4];
                #pragma unroll
                for (int half = 0; half < 2; half++) {
                    int tile = 2 * s + half;
                    float pe[4];
                    #pragma unroll
                    for (int e = 0; e < 4; e++) {
                        int dd  = ((e < 2) ? d0 : d1) - 8 * tile - (e & 1);
                        bool valid = (unsigned)dd <= (unsigned)WIN_;
                        pe[e] = valid ? exp2f(S[tile][e]) : 0.f;
                    }
                    l0 += pe[0] + pe[1];
                    l1 += pe[2] + pe[3];
                    pa[half * 2 + 0] = packh2(pe[0], pe[1]);
                    pa[half * 2 + 1] = packh2(pe[2], pe[3]);
                }

                uint32_t bv[4][4];
                #pragma unroll
                for (int nt = 0; nt < 4; nt++)
                    LDSM_X4(bv[nt][0], bv[nt][1], bv[nt][2], bv[nt][3],
                            vb + (nt * 16 + b_r) * VROW + s * 32 + b_c);
                #pragma unroll
                for (int dt = 0; dt < 8; dt++)
                    MMA_FP16(D[dt], pa, bv[dt >> 1][(dt & 1) * 2],
                             bv[dt >> 1][(dt & 1) * 2 + 1]);
            }
        }
    }

    l0 += __shfl_xor_sync(0xFFFFFFFFu, l0, 1);
    l0 += __shfl_xor_sync(0xFFFFFFFFu, l0, 2);
    l1 += __shfl_xor_sync(0xFFFFFFFFu, l1, 1);
    l1 += __shfl_xor_sync(0xFFFFFFFFu, l1, 2);
    const float inv0 = 1.f / l0;
    const float inv1 = 1.f / l1;

    const size_t r0m = (size_t)(m0 + gid) * KW_;
    const size_t r1m = (size_t)(m0 + gid + 8) * KW_;
    #pragma unroll
    for (int dt = 0; dt < 8; dt++) {
        int col = h * 64 + dt * 8 + tig * 2;
        *(uint32_t*)&g_As[r0m + col] = packh2(D[dt][0] * inv0, D[dt][1] * inv0);
        *(uint32_t*)&g_As[r1m + col] = packh2(D[dt][2] * inv1, D[dt][3] * inv1);
    }
}

// ---------------------------------------------------------------------------
extern "C" void kernel_launch(void* const* d_in, const int* in_sizes, int n_in,
                              void* d_out, int out_size) {
    const float* x  = (const float*)d_in[0];
    const float* Wq = (const float*)d_in[2];
    const float* Wk = (const float*)d_in[3];
    const float* Wv = (const float*)d_in[4];
    const float* Wf = (const float*)d_in[5];
    const float* bf = (const float*)d_in[6];
    float* out = (float*)d_out;

    __half *Xs, *As, *Wqkvs, *Wfs;
    cudaGetSymbolAddress((void**)&Xs,    g_Xs);
    cudaGetSymbolAddress((void**)&As,    g_As);
    cudaGetSymbolAddress((void**)&Wqkvs, g_Wqkvs);
    cudaGetSymbolAddress((void**)&Wfs,   g_Wfs);

    static int init = 0;
    if (!init) {
        cudaFuncSetAttribute(attn_mma, cudaFuncAttributeMaxDynamicSharedMemorySize,
                             ASTG * CHBUF);
        cudaFuncSetAttribute((const void*)gemm_mma<1>,
                             cudaFuncAttributeMaxDynamicSharedMemorySize, GSMEM);
        cudaFuncSetAttribute((const void*)gemm_mma<0>,
                             cudaFuncAttributeMaxDynamicSharedMemorySize, GSMEM);
        init = 1;
    }

    // fused conversions (hi-only fp16)
    conv_all<<<(XV4 + WV4 + 255) / 256, 256>>>(
        (const float4*)x, (const float4*)Wq, (const float4*)Wk,
        (const float4*)Wv, (const float4*)Wf);

    // fused QKV projection (128x128 tiles, 288 CTAs)
    gemm_mma<1><<<dim3(NQKV / 128, M_ / 128), 256, GSMEM>>>(Xs, Wqkvs, nullptr, nullptr, NQKV);

    // attention (fp16 tensor cores, 128-query tiles, per-warp chunk skip)
    attn_mma<<<dim3(T_ / 128, NH_ / 2, B_), 512, ASTG * CHBUF>>>();

    // output projection (+bias, 256 CTAs)
    gemm_mma<0><<<dim3(WID_ / 128, M_ / 128), 256, GSMEM>>>(As, Wfs, out, bf, WID_);
}